// round 2
// baseline (speedup 1.0000x reference)
#include <cuda_runtime.h>
#include <cstdint>
#include <cstddef>

// ---------------------------------------------------------------------------
// Helpers — PLAIN sm_100 features only (no tcgen05 / no 'a'-features).
// mma.sync tf32 (sm_80), ldmatrix b16 (sm_75), cp.async (sm_80).
// ---------------------------------------------------------------------------
__device__ __forceinline__ uint32_t smem_u32(const void* p) {
    uint32_t a;
    asm("{ .reg .u64 t; cvta.to.shared.u64 t, %1; cvt.u32.u64 %0, t; }"
        : "=r"(a) : "l"(p));
    return a;
}

__device__ __forceinline__ float to_tf32(float v) {
    uint32_t o;
    asm("cvt.rna.tf32.f32 %0, %1;" : "=r"(o) : "f"(v));
    return __uint_as_float(o);
}

#define LDSM4(r, addr)                                                         \
    asm volatile("ldmatrix.sync.aligned.m8n8.x4.shared.b16 {%0,%1,%2,%3}, [%4];" \
                 : "=r"((r)[0]), "=r"((r)[1]), "=r"((r)[2]), "=r"((r)[3])      \
                 : "r"(addr))

#define MMA_TF32(d, a, b0, b1)                                                 \
    asm volatile("mma.sync.aligned.m16n8k8.row.col.f32.tf32.tf32.f32 "         \
                 "{%0,%1,%2,%3}, {%4,%5,%6,%7}, {%8,%9}, {%0,%1,%2,%3};"       \
                 : "+f"((d)[0]), "+f"((d)[1]), "+f"((d)[2]), "+f"((d)[3])      \
                 : "r"((a)[0]), "r"((a)[1]), "r"((a)[2]), "r"((a)[3]),         \
                   "r"(b0), "r"(b1))

#define CP_ASYNC16(dst, src)                                                   \
    asm volatile("cp.async.cg.shared.global [%0], [%1], 16;"                   \
                 :: "r"(dst), "l"(src) : "memory")

#define CP_COMMIT()  asm volatile("cp.async.commit_group;" ::: "memory")
#define CP_WAIT(n)   asm volatile("cp.async.wait_group %0;" :: "n"(n) : "memory")

// ---------------------------------------------------------------------------
// Problem constants
// ---------------------------------------------------------------------------
static constexpr int B  = 8;
static constexpr int T  = 4096;
static constexpr int D  = 1024;
static constexpr int H  = 32;
static constexpr int MR = B * T;   // 32768 GEMM rows (t = 1..4096 per batch)

// Device-global scratch (no runtime allocation allowed)
__device__ float g_s[(size_t)MR * D];   // conv output, tf32-rounded
__device__ float g_wvt[D * D];          // Wv^T, tf32-rounded
__device__ float g_wor[D * D];          // Wo,   tf32-rounded
__device__ float g_wc[D * D];           // Wc = Wo @ Wv, tf32-rounded
__device__ float g_bc[D];               // fused bias

// ---------------------------------------------------------------------------
// Prep kernels
// ---------------------------------------------------------------------------
__global__ void round_wo_kernel(const float* __restrict__ Wo, float* __restrict__ wor) {
    int i = blockIdx.x * blockDim.x + threadIdx.x;
    if (i < D * D) wor[i] = to_tf32(Wo[i]);
}

__global__ void transpose_round_kernel(const float* __restrict__ Wv, float* __restrict__ wvt) {
    __shared__ float tile[32][33];
    int bx = blockIdx.x & 31, by = blockIdx.x >> 5;
    int tx = threadIdx.x & 31, ty = threadIdx.x >> 5;   // 32x8 threads
    int x0 = bx * 32, y0 = by * 32;
    #pragma unroll
    for (int yy = ty; yy < 32; yy += 8)
        tile[yy][tx] = Wv[(size_t)(y0 + yy) * D + x0 + tx];
    __syncthreads();
    #pragma unroll
    for (int yy = ty; yy < 32; yy += 8)
        wvt[(size_t)(x0 + yy) * D + y0 + tx] = to_tf32(tile[tx][yy]);
}

__global__ void bias_kernel(const float* __restrict__ Wo, const float* __restrict__ bv,
                            const float* __restrict__ bo, const float* __restrict__ dw,
                            float* __restrict__ bc) {
    int warp = threadIdx.x >> 5, lane = threadIdx.x & 31;
    int n = blockIdx.x * 8 + warp;
    float sw = dw[lane];
    #pragma unroll
    for (int o = 16; o; o >>= 1) sw += __shfl_xor_sync(0xFFFFFFFFu, sw, o);
    float acc = 0.f;
    const float* wrow = Wo + (size_t)n * D;
    #pragma unroll 4
    for (int j = lane; j < D; j += 32) acc += wrow[j] * bv[j];
    #pragma unroll
    for (int o = 16; o; o >>= 1) acc += __shfl_xor_sync(0xFFFFFFFFu, acc, o);
    if (lane == 0) bc[n] = acc * sw + bo[n];
}

__global__ void fill_t0_kernel(const float* __restrict__ bc, float* __restrict__ out) {
    out[(size_t)blockIdx.x * (T + 1) * D + threadIdx.x] = bc[threadIdx.x];
}

// ---------------------------------------------------------------------------
// Depthwise causal conv: s[b, tt, d] = sum_{i=0..31} w[i] * x[b, tt-31+i, d]
// 16 outputs per thread; output rounded to tf32.
// ---------------------------------------------------------------------------
static constexpr int CR = 16;

__global__ void __launch_bounds__(256) conv_kernel(const float* __restrict__ x,
                                                   const float* __restrict__ w,
                                                   float* __restrict__ s) {
    const int bid    = blockIdx.x;
    const int dchunk = bid & 3;                 // 4 chunks of 256 d
    const int tchunk = (bid >> 2) & (T / CR - 1);
    const int b      = bid >> 10;               // 4 * 256 = 1024 blocks per batch
    const int d      = dchunk * 256 + threadIdx.x;
    const int tt0    = tchunk * CR;

    float wr[H];
    #pragma unroll
    for (int i = 0; i < H; ++i) wr[i] = __ldg(&w[i]);

    float acc[CR];
    #pragma unroll
    for (int j = 0; j < CR; ++j) acc[j] = 0.f;

    const float* xb = x + ((size_t)b * T) * D + d;
    #pragma unroll
    for (int p = -(H - 1); p <= CR - 1; ++p) {
        int tp = tt0 + p;
        float v = (tp >= 0) ? xb[(size_t)tp * D] : 0.f;
        #pragma unroll
        for (int j = 0; j < CR; ++j) {
            int i = p + (H - 1) - j;
            if (i >= 0 && i < H) acc[j] = fmaf(wr[i], v, acc[j]);
        }
    }
    float* sp = s + ((size_t)(b * T + tt0)) * D + d;
    #pragma unroll
    for (int j = 0; j < CR; ++j) sp[(size_t)j * D] = to_tf32(acc[j]);
}

// ---------------------------------------------------------------------------
// tf32 mma.sync GEMM:  C[m,n] = sum_k A[m,k] * B[n,k]  (both K-major)
// CTA tile 128x128x32, 8 warps (warp tile 64x32), 3-stage cp.async pipeline.
// SMEM rows are exactly 128B -> SW128 swizzle == xor bits[4:6] with row&7.
// MODE 0: out[m*N+n] = tf32_round(C)        (weight-fuse GEMM)
// MODE 1: out[(b*4097 + t + 1)*D + n] = C + bias[n]   (main GEMM)
// ---------------------------------------------------------------------------
static constexpr int TM = 128, TN = 128, TK = 32, STG = 3;
static constexpr int STAGE_BYTES = (TM + TN) * TK * 4;   // 32768
static constexpr int GEMM_SMEM   = STG * STAGE_BYTES;    // 98304

template <int MODE>
__global__ void __launch_bounds__(256, 2)
gemm_tf32(const float* __restrict__ A, const float* __restrict__ Bm,
          const float* __restrict__ bias, float* __restrict__ out,
          int M, int K, int N) {
    extern __shared__ __align__(128) char smem[];
    const uint32_t tiles = smem_u32(smem);

    const int tid  = threadIdx.x;
    const int wid  = tid >> 5;
    const int lane = tid & 31;

    const int ntn    = N / TN;
    const int m_tile = blockIdx.x / ntn;
    const int n_tile = blockIdx.x % ntn;

    const int warp_m = (wid & 1) * 64;   // 2 warps in m
    const int warp_n = (wid >> 1) * 32;  // 4 warps in n

    // ---- cp.async stage loader: 256 rows x 8 chunks of 16B, 8 per thread ----
    auto load_stage = [&](int stage, int kt) {
        const uint32_t a_base = tiles + stage * STAGE_BYTES;
        const uint32_t b_base = a_base + TM * 128;
        #pragma unroll
        for (int it = 0; it < 8; ++it) {
            int c    = tid + it * 256;
            bool isA = c < TM * 8;
            int cc   = isA ? c : c - TM * 8;
            int row  = cc >> 3, ch = cc & 7;
            const float* src = isA
                ? A  + (size_t)(m_tile * TM + row) * K + kt * TK + ch * 4
                : Bm + (size_t)(n_tile * TN + row) * K + kt * TK + ch * 4;
            uint32_t dst = (isA ? a_base : b_base) + row * 128
                         + ((uint32_t)(ch * 16) ^ (uint32_t)((row & 7) << 4));
            CP_ASYNC16(dst, __cvta_generic_to_global(src));
        }
    };

    // ---- per-thread ldmatrix address constants ----
    const int r8  = lane & 7;
    const int sub = lane >> 3;
    const int koffA = (sub >> 1) * 16;   // A subtiles 2,3 take k+4
    const int koffB = (sub & 1) * 16;    // B subtiles 1,3 take k+4

    uint32_t aRow[4], aX[4], bRow[2], bX[2];
    #pragma unroll
    for (int mt = 0; mt < 4; ++mt) {
        int r = warp_m + mt * 16 + (sub & 1) * 8 + r8;
        aRow[mt] = (uint32_t)(r * 128);
        aX[mt]   = (uint32_t)((r & 7) << 4);
    }
    #pragma unroll
    for (int nt = 0; nt < 2; ++nt) {
        int r = warp_n + nt * 16 + (sub >> 1) * 8 + r8;
        bRow[nt] = (uint32_t)(r * 128);
        bX[nt]   = (uint32_t)((r & 7) << 4);
    }

    float acc[4][4][4];
    #pragma unroll
    for (int mt = 0; mt < 4; ++mt)
        #pragma unroll
        for (int j = 0; j < 4; ++j)
            #pragma unroll
            for (int e = 0; e < 4; ++e) acc[mt][j][e] = 0.f;

    const int KT = K / TK;

    // prologue: stages 0, 1
    load_stage(0, 0); CP_COMMIT();
    load_stage(1, 1); CP_COMMIT();

    int stage = 0;
    for (int kt = 0; kt < KT; ++kt) {
        CP_WAIT(STG - 2);
        __syncthreads();

        int ldk = kt + STG - 1;
        if (ldk < KT) {
            int lds = stage + STG - 1; if (lds >= STG) lds -= STG;
            load_stage(lds, ldk);
        }
        CP_COMMIT();

        const uint32_t a_base = tiles + stage * STAGE_BYTES;
        const uint32_t b_base = a_base + TM * 128;
        #pragma unroll
        for (int ks = 0; ks < 4; ++ks) {
            uint32_t af[4][4], bf[2][4];
            const uint32_t kb = (uint32_t)(ks * 32);
            #pragma unroll
            for (int nt = 0; nt < 2; ++nt)
                LDSM4(bf[nt], b_base + bRow[nt] + ((kb + koffB) ^ bX[nt]));
            #pragma unroll
            for (int mt = 0; mt < 4; ++mt)
                LDSM4(af[mt], a_base + aRow[mt] + ((kb + koffA) ^ aX[mt]));
            #pragma unroll
            for (int mt = 0; mt < 4; ++mt)
                #pragma unroll
                for (int j = 0; j < 4; ++j)
                    MMA_TF32(acc[mt][j], af[mt],
                             bf[j >> 1][(j & 1) * 2], bf[j >> 1][(j & 1) * 2 + 1]);
        }
        if (++stage == STG) stage = 0;
    }

    // ---- epilogue: direct float2 stores (fully-written 32B sectors) ----
    const int g = lane >> 2, q = lane & 3;
    #pragma unroll
    for (int j = 0; j < 4; ++j) {
        const int ncol = n_tile * TN + warp_n + j * 8 + q * 2;
        float2 bv2 = make_float2(0.f, 0.f);
        if (MODE == 1) bv2 = *reinterpret_cast<const float2*>(&bias[ncol]);
        #pragma unroll
        for (int mt = 0; mt < 4; ++mt) {
            #pragma unroll
            for (int h = 0; h < 2; ++h) {
                int m = m_tile * TM + warp_m + mt * 16 + g + h * 8;
                float v0 = acc[mt][j][h * 2 + 0] + bv2.x;
                float v1 = acc[mt][j][h * 2 + 1] + bv2.y;
                size_t oaddr;
                if (MODE == 1) {
                    int bb = m >> 12, t = m & 4095;
                    oaddr = (size_t)(bb * (T + 1) + t + 1) * D + ncol;
                } else {
                    v0 = to_tf32(v0); v1 = to_tf32(v1);
                    oaddr = (size_t)m * N + ncol;
                }
                *reinterpret_cast<float2*>(&out[oaddr]) = make_float2(v0, v1);
            }
        }
    }
}

// ---------------------------------------------------------------------------
// launch
// ---------------------------------------------------------------------------
extern "C" void kernel_launch(void* const* d_in, const int* in_sizes, int n_in,
                              void* d_out, int out_size) {
    (void)in_sizes; (void)n_in; (void)out_size;
    const float* x  = (const float*)d_in[0];
    const float* Wv = (const float*)d_in[1];
    const float* bv = (const float*)d_in[2];
    const float* Wo = (const float*)d_in[3];
    const float* bo = (const float*)d_in[4];
    const float* dw = (const float*)d_in[5];
    float* out = (float*)d_out;

    float *s, *wvt, *wor, *wc, *bc;
    cudaGetSymbolAddress((void**)&s,   g_s);
    cudaGetSymbolAddress((void**)&wvt, g_wvt);
    cudaGetSymbolAddress((void**)&wor, g_wor);
    cudaGetSymbolAddress((void**)&wc,  g_wc);
    cudaGetSymbolAddress((void**)&bc,  g_bc);

    cudaFuncSetAttribute(gemm_tf32<0>, cudaFuncAttributeMaxDynamicSharedMemorySize, GEMM_SMEM);
    cudaFuncSetAttribute(gemm_tf32<1>, cudaFuncAttributeMaxDynamicSharedMemorySize, GEMM_SMEM);

    // prep: round/transpose weights, fused bias
    round_wo_kernel<<<(D * D + 511) / 512, 512>>>(Wo, wor);
    transpose_round_kernel<<<1024, 256>>>(Wv, wvt);
    bias_kernel<<<D / 8, 256>>>(Wo, bv, bo, dw, bc);

    // Wc = Wo @ Wv  (tf32 GEMM, M=N=K=1024)
    gemm_tf32<0><<<(D / TM) * (D / TN), 256, GEMM_SMEM>>>(wor, wvt, nullptr, wc, D, D, D);

    // depthwise conv -> s (tf32-rounded)
    conv_kernel<<<B * (T / CR) * (D / 256), 256>>>(x, dw, s);

    // out[b, 0, :] = bc
    fill_t0_kernel<<<B, D>>>(bc, out);

    // out[b, 1.., :] = s @ Wc^T + bc
    gemm_tf32<1><<<(MR / TM) * (D / TN), 256, GEMM_SMEM>>>(s, wc, bc, out, MR, D, D);
}

// round 3
// speedup vs baseline: 1.5169x; 1.5169x over previous
#include <cuda_runtime.h>
#include <cuda_fp16.h>
#include <cstdint>
#include <cstddef>

// ---------------------------------------------------------------------------
// Helpers — PLAIN sm_100 features only (no tcgen05 / no 'a'-features).
// mma.sync fp16 m16n8k16 (sm_80), ldmatrix b16 (sm_75), cp.async (sm_80).
// ---------------------------------------------------------------------------
__device__ __forceinline__ uint32_t smem_u32(const void* p) {
    uint32_t a;
    asm("{ .reg .u64 t; cvta.to.shared.u64 t, %1; cvt.u32.u64 %0, t; }"
        : "=r"(a) : "l"(p));
    return a;
}

#define LDSM4(r, addr)                                                         \
    asm volatile("ldmatrix.sync.aligned.m8n8.x4.shared.b16 {%0,%1,%2,%3}, [%4];" \
                 : "=r"((r)[0]), "=r"((r)[1]), "=r"((r)[2]), "=r"((r)[3])      \
                 : "r"(addr))

#define MMA_F16(d, a, b0, b1)                                                  \
    asm volatile("mma.sync.aligned.m16n8k16.row.col.f32.f16.f16.f32 "          \
                 "{%0,%1,%2,%3}, {%4,%5,%6,%7}, {%8,%9}, {%0,%1,%2,%3};"       \
                 : "+f"((d)[0]), "+f"((d)[1]), "+f"((d)[2]), "+f"((d)[3])      \
                 : "r"((a)[0]), "r"((a)[1]), "r"((a)[2]), "r"((a)[3]),         \
                   "r"(b0), "r"(b1))

#define CP_ASYNC16(dst, src)                                                   \
    asm volatile("cp.async.cg.shared.global [%0], [%1], 16;"                   \
                 :: "r"(dst), "l"(src) : "memory")

#define CP_COMMIT()  asm volatile("cp.async.commit_group;" ::: "memory")
#define CP_WAIT(n)   asm volatile("cp.async.wait_group %0;" :: "n"(n) : "memory")

// ---------------------------------------------------------------------------
// Problem constants
// ---------------------------------------------------------------------------
static constexpr int B  = 8;
static constexpr int T  = 4096;
static constexpr int D  = 1024;
static constexpr int H  = 32;
static constexpr int MR = B * T;   // 32768 GEMM rows (t = 1..4096 per batch)

// Device-global scratch (no runtime allocation allowed)
__device__ __half g_s[(size_t)MR * D];  // conv output, fp16
__device__ __half g_wvt[D * D];         // Wv^T, fp16
__device__ __half g_wor[D * D];         // Wo,   fp16
__device__ __half g_wc[D * D];          // Wc = Wo @ Wv, fp16
__device__ float  g_bc[D];              // fused bias (fp32)

// ---------------------------------------------------------------------------
// Prep kernels
// ---------------------------------------------------------------------------
__global__ void round_wo_kernel(const float* __restrict__ Wo, __half* __restrict__ wor) {
    int i = blockIdx.x * blockDim.x + threadIdx.x;
    if (i < D * D) wor[i] = __float2half_rn(Wo[i]);
}

__global__ void transpose_round_kernel(const float* __restrict__ Wv, __half* __restrict__ wvt) {
    __shared__ float tile[32][33];
    int bx = blockIdx.x & 31, by = blockIdx.x >> 5;
    int tx = threadIdx.x & 31, ty = threadIdx.x >> 5;   // 32x8 threads
    int x0 = bx * 32, y0 = by * 32;
    #pragma unroll
    for (int yy = ty; yy < 32; yy += 8)
        tile[yy][tx] = Wv[(size_t)(y0 + yy) * D + x0 + tx];
    __syncthreads();
    #pragma unroll
    for (int yy = ty; yy < 32; yy += 8)
        wvt[(size_t)(x0 + yy) * D + y0 + tx] = __float2half_rn(tile[tx][yy]);
}

__global__ void bias_kernel(const float* __restrict__ Wo, const float* __restrict__ bv,
                            const float* __restrict__ bo, const float* __restrict__ dw,
                            float* __restrict__ bc) {
    int warp = threadIdx.x >> 5, lane = threadIdx.x & 31;
    int n = blockIdx.x * 8 + warp;
    float sw = dw[lane];
    #pragma unroll
    for (int o = 16; o; o >>= 1) sw += __shfl_xor_sync(0xFFFFFFFFu, sw, o);
    float acc = 0.f;
    const float* wrow = Wo + (size_t)n * D;
    #pragma unroll 4
    for (int j = lane; j < D; j += 32) acc += wrow[j] * bv[j];
    #pragma unroll
    for (int o = 16; o; o >>= 1) acc += __shfl_xor_sync(0xFFFFFFFFu, acc, o);
    if (lane == 0) bc[n] = acc * sw + bo[n];
}

__global__ void fill_t0_kernel(const float* __restrict__ bc, float* __restrict__ out) {
    out[(size_t)blockIdx.x * (T + 1) * D + threadIdx.x] = bc[threadIdx.x];
}

// ---------------------------------------------------------------------------
// Depthwise causal conv: s[b, tt, d] = sum_{i=0..31} w[i] * x[b, tt-31+i, d]
// 32 outputs per thread (halo amortization 1.97x); fp32 math, fp16 store.
// ---------------------------------------------------------------------------
static constexpr int CR = 32;

__global__ void __launch_bounds__(256) conv_kernel(const float* __restrict__ x,
                                                   const float* __restrict__ w,
                                                   __half* __restrict__ s) {
    const int bid    = blockIdx.x;
    const int dchunk = bid & 3;                  // 4 chunks of 256 d
    const int tchunk = (bid >> 2) & (T / CR - 1);
    const int b      = bid >> 9;                 // 4 * 128 = 512 blocks per batch
    const int d      = dchunk * 256 + threadIdx.x;
    const int tt0    = tchunk * CR;

    float wr[H];
    #pragma unroll
    for (int i = 0; i < H; ++i) wr[i] = __ldg(&w[i]);

    float acc[CR];
    #pragma unroll
    for (int j = 0; j < CR; ++j) acc[j] = 0.f;

    const float* xb = x + ((size_t)b * T) * D + d;
    #pragma unroll
    for (int p = -(H - 1); p <= CR - 1; ++p) {
        int tp = tt0 + p;
        float v = (tp >= 0) ? xb[(size_t)tp * D] : 0.f;
        #pragma unroll
        for (int j = 0; j < CR; ++j) {
            int i = p + (H - 1) - j;
            if (i >= 0 && i < H) acc[j] = fmaf(wr[i], v, acc[j]);
        }
    }
    __half* sp = s + ((size_t)(b * T + tt0)) * D + d;
    #pragma unroll
    for (int j = 0; j < CR; ++j) sp[(size_t)j * D] = __float2half_rn(acc[j]);
}

// ---------------------------------------------------------------------------
// fp16 mma.sync GEMM:  C[m,n] = sum_k A[m,k] * B[n,k]  (both K-major, fp16)
// CTA tile 128x128x64(halves), 8 warps (warp tile 64x32), 3-stage cp.async.
// SMEM rows are exactly 128B -> SW128 swizzle == xor bits[4:6] with row&7.
// MODE 0: outh[m*N+n] = fp16(C)                       (weight-fuse GEMM)
// MODE 1: outf[(b*4097 + t + 1)*D + n] = C + bias[n]  (main GEMM)
// ---------------------------------------------------------------------------
static constexpr int TM = 128, TN = 128, TK = 64, STG = 3;
static constexpr int STAGE_BYTES = (TM + TN) * TK * 2;   // 32768
static constexpr int GEMM_SMEM   = STG * STAGE_BYTES;    // 98304

template <int MODE>
__global__ void __launch_bounds__(256, 2)
gemm_f16(const __half* __restrict__ A, const __half* __restrict__ Bm,
         const float* __restrict__ bias, float* __restrict__ outf,
         __half* __restrict__ outh, int M, int K, int N) {
    extern __shared__ __align__(128) char smem[];
    const uint32_t tiles = smem_u32(smem);

    const int tid  = threadIdx.x;
    const int wid  = tid >> 5;
    const int lane = tid & 31;

    const int ntn    = N / TN;
    const int m_tile = blockIdx.x / ntn;
    const int n_tile = blockIdx.x % ntn;

    const int warp_m = (wid & 1) * 64;   // 2 warps in m
    const int warp_n = (wid >> 1) * 32;  // 4 warps in n

    // ---- cp.async stage loader: 256 rows x 8 chunks of 16B, 8 per thread ----
    auto load_stage = [&](int stage, int kt) {
        const uint32_t a_base = tiles + stage * STAGE_BYTES;
        const uint32_t b_base = a_base + TM * 128;
        #pragma unroll
        for (int it = 0; it < 8; ++it) {
            int c    = tid + it * 256;
            bool isA = c < TM * 8;
            int cc   = isA ? c : c - TM * 8;
            int row  = cc >> 3, ch = cc & 7;     // ch: 16B (8-half) chunk
            const __half* src = isA
                ? A  + (size_t)(m_tile * TM + row) * K + kt * TK + ch * 8
                : Bm + (size_t)(n_tile * TN + row) * K + kt * TK + ch * 8;
            uint32_t dst = (isA ? a_base : b_base) + row * 128
                         + ((uint32_t)(ch * 16) ^ (uint32_t)((row & 7) << 4));
            CP_ASYNC16(dst, __cvta_generic_to_global(src));
        }
    };

    // ---- per-thread ldmatrix address constants ----
    // x4 tiles: sub0: rows+0..7 k+0; sub1: rows+8..15 k+0; sub2: rows+0..7 k+8h; sub3: rows+8..15 k+8h
    const int r8  = lane & 7;
    const int sub = lane >> 3;
    const uint32_t koff = (uint32_t)((sub >> 1) * 16);   // +16B for k+8 halves

    uint32_t aRow[4], aX[4], bRow[2], bX[2];
    #pragma unroll
    for (int mt = 0; mt < 4; ++mt) {
        int r = warp_m + mt * 16 + (sub & 1) * 8 + r8;
        aRow[mt] = (uint32_t)(r * 128);
        aX[mt]   = (uint32_t)((r & 7) << 4);
    }
    #pragma unroll
    for (int nt = 0; nt < 2; ++nt) {
        int r = warp_n + nt * 16 + (sub & 1) * 8 + r8;
        bRow[nt] = (uint32_t)(r * 128);
        bX[nt]   = (uint32_t)((r & 7) << 4);
    }

    float acc[4][4][4];
    #pragma unroll
    for (int mt = 0; mt < 4; ++mt)
        #pragma unroll
        for (int j = 0; j < 4; ++j)
            #pragma unroll
            for (int e = 0; e < 4; ++e) acc[mt][j][e] = 0.f;

    const int KT = K / TK;

    // prologue: stages 0, 1
    load_stage(0, 0); CP_COMMIT();
    load_stage(1, 1); CP_COMMIT();

    int stage = 0;
    for (int kt = 0; kt < KT; ++kt) {
        CP_WAIT(STG - 2);
        __syncthreads();

        int ldk = kt + STG - 1;
        if (ldk < KT) {
            int lds = stage + STG - 1; if (lds >= STG) lds -= STG;
            load_stage(lds, ldk);
        }
        CP_COMMIT();

        const uint32_t a_base = tiles + stage * STAGE_BYTES;
        const uint32_t b_base = a_base + TM * 128;
        #pragma unroll
        for (int ks = 0; ks < 4; ++ks) {            // 4 k-steps of 16 halves
            uint32_t af[4][4], bf[2][4];
            const uint32_t kb = (uint32_t)(ks * 32);  // 16 halves = 32B
            #pragma unroll
            for (int nt = 0; nt < 2; ++nt)
                LDSM4(bf[nt], b_base + bRow[nt] + ((kb + koff) ^ bX[nt]));
            #pragma unroll
            for (int mt = 0; mt < 4; ++mt)
                LDSM4(af[mt], a_base + aRow[mt] + ((kb + koff) ^ aX[mt]));
            // bf[nt]: r0 = n0-7,k0-7 ; r1 = n8-15,k0-7 ; r2 = n0-7,k8-15 ; r3 = n8-15,k8-15
            #pragma unroll
            for (int mt = 0; mt < 4; ++mt)
                #pragma unroll
                for (int j = 0; j < 4; ++j)
                    MMA_F16(acc[mt][j], af[mt],
                            bf[j >> 1][j & 1], bf[j >> 1][(j & 1) + 2]);
        }
        if (++stage == STG) stage = 0;
    }

    // ---- epilogue: direct paired stores (fully-written 32B sectors) ----
    const int g = lane >> 2, q = lane & 3;
    #pragma unroll
    for (int j = 0; j < 4; ++j) {
        const int ncol = n_tile * TN + warp_n + j * 8 + q * 2;
        float2 bv2 = make_float2(0.f, 0.f);
        if (MODE == 1) bv2 = *reinterpret_cast<const float2*>(&bias[ncol]);
        #pragma unroll
        for (int mt = 0; mt < 4; ++mt) {
            #pragma unroll
            for (int h = 0; h < 2; ++h) {
                int m = m_tile * TM + warp_m + mt * 16 + g + h * 8;
                float v0 = acc[mt][j][h * 2 + 0] + bv2.x;
                float v1 = acc[mt][j][h * 2 + 1] + bv2.y;
                if (MODE == 1) {
                    int bb = m >> 12, t = m & 4095;
                    size_t oaddr = (size_t)(bb * (T + 1) + t + 1) * D + ncol;
                    *reinterpret_cast<float2*>(&outf[oaddr]) = make_float2(v0, v1);
                } else {
                    size_t oaddr = (size_t)m * N + ncol;
                    __half2 hv = __floats2half2_rn(v0, v1);
                    *reinterpret_cast<__half2*>(&outh[oaddr]) = hv;
                }
            }
        }
    }
}

// ---------------------------------------------------------------------------
// launch
// ---------------------------------------------------------------------------
extern "C" void kernel_launch(void* const* d_in, const int* in_sizes, int n_in,
                              void* d_out, int out_size) {
    (void)in_sizes; (void)n_in; (void)out_size;
    const float* x  = (const float*)d_in[0];
    const float* Wv = (const float*)d_in[1];
    const float* bv = (const float*)d_in[2];
    const float* Wo = (const float*)d_in[3];
    const float* bo = (const float*)d_in[4];
    const float* dw = (const float*)d_in[5];
    float* out = (float*)d_out;

    __half *s, *wvt, *wor, *wc;
    float  *bc;
    cudaGetSymbolAddress((void**)&s,   g_s);
    cudaGetSymbolAddress((void**)&wvt, g_wvt);
    cudaGetSymbolAddress((void**)&wor, g_wor);
    cudaGetSymbolAddress((void**)&wc,  g_wc);
    cudaGetSymbolAddress((void**)&bc,  g_bc);

    cudaFuncSetAttribute(gemm_f16<0>, cudaFuncAttributeMaxDynamicSharedMemorySize, GEMM_SMEM);
    cudaFuncSetAttribute(gemm_f16<1>, cudaFuncAttributeMaxDynamicSharedMemorySize, GEMM_SMEM);

    // prep: round/transpose weights, fused bias
    round_wo_kernel<<<(D * D + 511) / 512, 512>>>(Wo, wor);
    transpose_round_kernel<<<1024, 256>>>(Wv, wvt);
    bias_kernel<<<D / 8, 256>>>(Wo, bv, bo, dw, bc);

    // Wc = Wo @ Wv  (fp16 GEMM, M=N=K=1024)
    gemm_f16<0><<<(D / TM) * (D / TN), 256, GEMM_SMEM>>>(wor, wvt, nullptr, nullptr, wc, D, D, D);

    // depthwise conv -> s (fp16)
    conv_kernel<<<B * (T / CR) * (D / 256), 256>>>(x, dw, s);

    // out[b, 0, :] = bc
    fill_t0_kernel<<<B, D>>>(bc, out);

    // out[b, 1.., :] = s @ Wc^T + bc
    gemm_f16<1><<<(MR / TM) * (D / TN), 256, GEMM_SMEM>>>(s, wc, bc, out, nullptr, MR, D, D);
}